// round 15
// baseline (speedup 1.0000x reference)
#include <cuda_runtime.h>
#include <cstdint>
#include <cstring>

#define NB 32768
#define NM 8192
#define KNN 16
#define NROWBLK (NB / 128)
#define GD 64
#define GC2 (GD * GD)
#define GLO (-6.0f)
#define GINV 5.3333333333f     // 1 / (12/64)
#define SEEDW 128              // half-width of Morton seed window
#define CH 32                  // chunk size for branchless dense scan

// ---------------- scratch (device globals; no allocations allowed) ----------
__device__ float  g_bufA[NB * 512];
__device__ float  g_bufB[NB * 512];
__device__ float  g_X1[NB * 80];
__device__ float  g_pS[NROWBLK * 512];
__device__ float  g_pSS[NROWBLK * 512];
__device__ float  g_scale[512];
__device__ float  g_shift[512];
__device__ int    g_mCnt[GC2];
__device__ int    g_mCur[GC2];
__device__ int    g_qCnt[GC2];
__device__ int    g_qCur[GC2];
__device__ int    g_qperm[NB];
__device__ float4 g_mcS[NM];     // MORTON-sorted (x, y, |m|^2, orig-idx bits)

// packed f32x2 fma helpers (FFMA2)
#define FMA2(d, a, b) \
    asm("fma.rn.f32x2 %0, %1, %2, %0;" : "+l"(d) : "l"(a), "l"(b))
#define PACK2(d, s) \
    asm("mov.b64 %0, {%1, %1};" : "=l"(d) : "r"(__float_as_uint(s)))

__device__ __forceinline__ float2 unpack2(unsigned long long v) {
    float2 f; memcpy(&f, &v, 8); return f;
}

// ---------------- morton helpers ---------------------------------------------
__device__ __forceinline__ int cell_x(float x) {
    int c = (int)floorf((x - GLO) * GINV);
    return min(GD - 1, max(0, c));
}
__device__ __forceinline__ unsigned morton_part(unsigned v) {
    v &= 63u;
    v = (v | (v << 4)) & 0x0F0Fu;
    v = (v | (v << 2)) & 0x3333u;
    v = (v | (v << 1)) & 0x5555u;
    return v;
}
__device__ __forceinline__ int morton_of(float x, float y) {
    return (int)(morton_part((unsigned)cell_x(x)) |
                 (morton_part((unsigned)cell_x(y)) << 1));
}

// ---------------- build kernels ----------------------------------------------
__global__ void grid_zero_kernel() {
    int i = blockIdx.x * blockDim.x + threadIdx.x;
    if (i < GC2) { g_mCnt[i] = 0; g_qCnt[i] = 0; }
}

__global__ void grid_count_kernel(const float* __restrict__ pos,
                                  const float* __restrict__ mc) {
    int i = blockIdx.x * blockDim.x + threadIdx.x;
    if (i < NM) {
        float2 c = ((const float2*)mc)[i];
        atomicAdd(&g_mCnt[morton_of(c.x, c.y)], 1);
    }
    float2 p = ((const float2*)pos)[i];
    atomicAdd(&g_qCnt[morton_of(p.x, p.y)], 1);
}

__global__ void grid_scan_kernel() {   // 1 block, 256 threads; 16 cells/thread
    __shared__ int bs[256];
    int t = threadIdx.x;
    int base = t << 4;
    int loc[16];
    int s = 0;
#pragma unroll
    for (int k = 0; k < 16; ++k) { loc[k] = s; s += g_mCnt[base + k]; }
    bs[t] = s;
    __syncthreads();
    if (t == 0) { int a = 0; for (int i = 0; i < 256; ++i) { int c = bs[i]; bs[i] = a; a += c; } }
    __syncthreads();
#pragma unroll
    for (int k = 0; k < 16; ++k) g_mCur[base + k] = bs[t] + loc[k];
    __syncthreads();
    s = 0;
#pragma unroll
    for (int k = 0; k < 16; ++k) { loc[k] = s; s += g_qCnt[base + k]; }
    bs[t] = s;
    __syncthreads();
    if (t == 0) { int a = 0; for (int i = 0; i < 256; ++i) { int c = bs[i]; bs[i] = a; a += c; } }
    __syncthreads();
#pragma unroll
    for (int k = 0; k < 16; ++k) g_qCur[base + k] = bs[t] + loc[k];
}

__global__ void grid_scatter_kernel(const float* __restrict__ pos,
                                    const float* __restrict__ mc) {
    int i = blockIdx.x * blockDim.x + threadIdx.x;
    if (i < NM) {
        float2 c = ((const float2*)mc)[i];
        float mm = __fadd_rn(__fmul_rn(c.x, c.x), __fmul_rn(c.y, c.y));
        int slot = atomicAdd(&g_mCur[morton_of(c.x, c.y)], 1);
        g_mcS[slot] = make_float4(c.x, c.y, mm, __int_as_float(i));
    }
    float2 p = ((const float2*)pos)[i];
    int slot = atomicAdd(&g_qCur[morton_of(p.x, p.y)], 1);
    g_qperm[slot] = i;
}

// ---------------- KNN: Morton seed + branchless chunk-min dense scan ---------
// Seed window: per-point insert scan (inserts common there).
// Dense complements: 32-point branchless min-scan; rescan chunk only if its
// min beats bd[15] (rare post-seed). No BSSY/BSYNC in the hot loop.
// Every j visited exactly once; selection = min-16 under total order (d2,idx)
// == stable lax.top_k. d2 rounding identical to the verified R6 formula.
extern __shared__ float4 knn_tile[];

__global__ void knn_kernel(const float* __restrict__ pos,
                           const float* __restrict__ mc,
                           const float* __restrict__ mv,
                           float* __restrict__ knn_out,   // [B,66]
                           float* __restrict__ x1pad)     // [B,80]
{
    const int tid = threadIdx.x;
    for (int j = tid; j < NM; j += blockDim.x) knn_tile[j] = g_mcS[j];
    __syncthreads();

    const int row = g_qperm[blockIdx.x * blockDim.x + tid];
    const float2 p = ((const float2*)pos)[row];
    const float pp = __fadd_rn(__fmul_rn(p.x, p.x), __fmul_rn(p.y, p.y));

    // warp-uniform window: binary search lane-0's Morton code in the tile
    int mcode0 = __shfl_sync(0xffffffffu, morton_of(p.x, p.y), 0);
    int lo = 0, hi = NM;
#pragma unroll
    for (int it = 0; it < 13; ++it) {
        int mid = (lo + hi) >> 1;
        float4 q = knn_tile[mid];
        int code = morton_of(q.x, q.y);
        if (code < mcode0) lo = mid + 1; else hi = mid;
    }
    const int wlo = max(0, lo - SEEDW);
    const int whi = min(NM, lo + SEEDW);

    float bd[KNN];
    int   bi[KNN];
#pragma unroll
    for (int t = 0; t < KNN; ++t) { bd[t] = 3.4e38f; bi[t] = 0x7fffffff; }

    auto d2_of = [&](float4 q) {
        float dot = __fmaf_rn(p.y, q.y, __fmul_rn(p.x, q.x));
        float s   = __fadd_rn(pp, q.z);
        return __fmaf_rn(-2.0f, dot, s);
    };

    auto insert = [&](float d2, int idx) {
        if (d2 < bd[KNN - 1] ||
            (d2 == bd[KNN - 1] && idx < bi[KNN - 1])) {
            bd[KNN - 1] = d2;
            bi[KNN - 1] = idx;
#pragma unroll
            for (int t = KNN - 1; t >= 1; --t) {
                bool sw = (bd[t] < bd[t - 1]) ||
                          (bd[t] == bd[t - 1] && bi[t] < bi[t - 1]);
                float td = bd[t]; int ti = bi[t];
                if (sw) {
                    bd[t] = bd[t - 1]; bi[t] = bi[t - 1];
                    bd[t - 1] = td;    bi[t - 1] = ti;
                }
            }
        }
    };

    // phase 1: seed window, per-point insert path
    for (int j = wlo; j < whi; ++j) {
        float4 q = knn_tile[j];
        float d2 = d2_of(q);
        if (d2 <= bd[KNN - 1]) insert(d2, __float_as_int(q.w));
    }

    // phase 2: dense complements, branchless chunk-min screening
    auto scan_dense = [&](int rlo, int rhi) {
        int j = rlo;
        for (; j + CH <= rhi; j += CH) {
            float cmin = 3.4e38f;
#pragma unroll
            for (int u = 0; u < CH; ++u)
                cmin = fminf(cmin, d2_of(knn_tile[j + u]));
            if (cmin <= bd[KNN - 1]) {
                for (int u = 0; u < CH; ++u) {
                    float4 q = knn_tile[j + u];
                    float d2 = d2_of(q);
                    if (d2 <= bd[KNN - 1]) insert(d2, __float_as_int(q.w));
                }
            }
        }
        for (; j < rhi; ++j) {
            float4 q = knn_tile[j];
            float d2 = d2_of(q);
            if (d2 <= bd[KNN - 1]) insert(d2, __float_as_int(q.w));
        }
    };
    scan_dense(0, wlo);
    scan_dense(whi, NM);

    float* o1 = knn_out + (size_t)row * 66;
    float* o2 = x1pad + (size_t)row * 80;
    o1[0] = p.x; o1[1] = p.y;
    o2[0] = p.x; o2[1] = p.y;
#pragma unroll
    for (int t = 0; t < KNN; ++t) {
        int i = bi[t];
        float2 c = ((const float2*)mc)[i];
        float2 v = ((const float2*)mv)[i];
        int base = 2 + 4 * t;
        o1[base + 0] = c.x; o1[base + 1] = c.y; o1[base + 2] = v.x; o1[base + 3] = v.y;
        o2[base + 0] = c.x; o2[base + 1] = c.y; o2[base + 2] = v.x; o2[base + 3] = v.y;
    }
#pragma unroll
    for (int t = 66; t < 80; ++t) o2[t] = 0.0f;
}

// ---------------- GEMM: FFMA2 row-pair packed (R12, proven) ------------------
__global__ __launch_bounds__(256, 2)
void gemm_bn(const float* __restrict__ X, const float* __restrict__ W,
             const float* __restrict__ bias,
             const float* __restrict__ scale, const float* __restrict__ shift,
             float* __restrict__ Y, float* __restrict__ pS, float* __restrict__ pSS,
             int CinX, int CinW, int Cout, int useBN)
{
    __shared__ float As[16][132];
    __shared__ float Bs[16][128];
    __shared__ float sRed[16][128];

    const int tid = threadIdx.x;
    const int tx = tid & 15, ty = tid >> 4;
    const int n0 = blockIdx.x << 7;
    const int m0 = blockIdx.y << 7;

    unsigned long long acc[4][8];
#pragma unroll
    for (int r = 0; r < 4; ++r)
#pragma unroll
        for (int c = 0; c < 8; ++c) acc[r][c] = 0ull;

    const int nkt = CinX >> 4;
    for (int kt = 0; kt < nkt; ++kt) {
        const int k0 = kt << 4;
#pragma unroll
        for (int i = 0; i < 2; ++i) {
            int idx = tid + (i << 8);
            int r = idx >> 2, c4 = idx & 3;
            const float* xp = X + (size_t)(m0 + r) * CinX + k0 + (c4 << 2);
            float4 v = *(const float4*)xp;
            if (useBN) {
                float4 sc = *(const float4*)(scale + k0 + (c4 << 2));
                float4 sh = *(const float4*)(shift + k0 + (c4 << 2));
                v.x = fmaxf(fmaf(v.x, sc.x, sh.x), 0.0f);
                v.y = fmaxf(fmaf(v.y, sc.y, sh.y), 0.0f);
                v.z = fmaxf(fmaf(v.z, sc.z, sh.z), 0.0f);
                v.w = fmaxf(fmaf(v.w, sc.w, sh.w), 0.0f);
            }
            As[(c4 << 2) + 0][r] = v.x;
            As[(c4 << 2) + 1][r] = v.y;
            As[(c4 << 2) + 2][r] = v.z;
            As[(c4 << 2) + 3][r] = v.w;
        }
#pragma unroll
        for (int i = 0; i < 2; ++i) {
            int idx = tid + (i << 8);
            int kr = idx >> 5, c = idx & 31;
            int krow = k0 + kr, col = n0 + (c << 2);
            float4 v = make_float4(0.f, 0.f, 0.f, 0.f);
            if (krow < CinW && col < Cout)
                v = *(const float4*)(W + (size_t)krow * Cout + col);
            *(float4*)&Bs[kr][c << 2] = v;
        }
        __syncthreads();
#pragma unroll
        for (int kk = 0; kk < 16; ++kk) {
            ulonglong2 A0 = *(const ulonglong2*)&As[kk][ty << 2];
            ulonglong2 A1 = *(const ulonglong2*)&As[kk][64 + (ty << 2)];
            unsigned long long ap[4] = {A0.x, A0.y, A1.x, A1.y};
            float4 b0 = *(const float4*)&Bs[kk][tx << 2];
            float4 b1 = *(const float4*)&Bs[kk][64 + (tx << 2)];
            unsigned long long bp[8];
            PACK2(bp[0], b0.x); PACK2(bp[1], b0.y);
            PACK2(bp[2], b0.z); PACK2(bp[3], b0.w);
            PACK2(bp[4], b1.x); PACK2(bp[5], b1.y);
            PACK2(bp[6], b1.z); PACK2(bp[7], b1.w);
#pragma unroll
            for (int r = 0; r < 4; ++r)
#pragma unroll
                for (int c = 0; c < 8; ++c) FMA2(acc[r][c], ap[r], bp[c]);
        }
        __syncthreads();
    }

    float csum[8], csq[8];
#pragma unroll
    for (int c = 0; c < 8; ++c) { csum[c] = 0.f; csq[c] = 0.f; }

#pragma unroll
    for (int rr = 0; rr < 8; ++rr) {
        int rloc = (rr < 4) ? ((ty << 2) + rr) : (64 + (ty << 2) + rr - 4);
        int row = m0 + rloc;
        const int rp = rr >> 1;
        const bool hi = (rr & 1) != 0;
#pragma unroll
        for (int g2 = 0; g2 < 2; ++g2) {
            int colloc = (g2 << 6) + (tx << 2);
            int col = n0 + colloc;
            if (col < Cout) {
                float2 q0 = unpack2(acc[rp][g2 * 4 + 0]);
                float2 q1 = unpack2(acc[rp][g2 * 4 + 1]);
                float2 q2 = unpack2(acc[rp][g2 * 4 + 2]);
                float2 q3 = unpack2(acc[rp][g2 * 4 + 3]);
                float4 bb = *(const float4*)(bias + col);
                float4 o;
                o.x = (hi ? q0.y : q0.x) + bb.x;
                o.y = (hi ? q1.y : q1.x) + bb.y;
                o.z = (hi ? q2.y : q2.x) + bb.z;
                o.w = (hi ? q3.y : q3.x) + bb.w;
                *(float4*)(Y + (size_t)row * Cout + col) = o;
                csum[g2 * 4 + 0] += o.x; csq[g2 * 4 + 0] += o.x * o.x;
                csum[g2 * 4 + 1] += o.y; csq[g2 * 4 + 1] += o.y * o.y;
                csum[g2 * 4 + 2] += o.z; csq[g2 * 4 + 2] += o.z * o.z;
                csum[g2 * 4 + 3] += o.w; csq[g2 * 4 + 3] += o.w * o.w;
            }
        }
    }

    *(float4*)&sRed[ty][tx << 2]        = make_float4(csum[0], csum[1], csum[2], csum[3]);
    *(float4*)&sRed[ty][64 + (tx << 2)] = make_float4(csum[4], csum[5], csum[6], csum[7]);
    __syncthreads();
    if (tid < 128) {
        float s = 0.f;
#pragma unroll
        for (int t = 0; t < 16; ++t) s += sRed[t][tid];
        if (n0 + tid < Cout) pS[blockIdx.y * Cout + n0 + tid] = s;
    }
    __syncthreads();
    *(float4*)&sRed[ty][tx << 2]        = make_float4(csq[0], csq[1], csq[2], csq[3]);
    *(float4*)&sRed[ty][64 + (tx << 2)] = make_float4(csq[4], csq[5], csq[6], csq[7]);
    __syncthreads();
    if (tid < 128) {
        float s = 0.f;
#pragma unroll
        for (int t = 0; t < 16; ++t) s += sRed[t][tid];
        if (n0 + tid < Cout) pSS[blockIdx.y * Cout + n0 + tid] = s;
    }
}

// ---------------- BN stats fold ----------------------------------------------
__global__ void bnstats_kernel(const float* __restrict__ pS, const float* __restrict__ pSS,
                               const float* __restrict__ g, const float* __restrict__ be,
                               float* __restrict__ scale, float* __restrict__ shift, int Cout)
{
    int c = blockIdx.x * blockDim.x + threadIdx.x;
    if (c >= Cout) return;
    float s = 0.f, ss = 0.f;
    for (int r = 0; r < NROWBLK; ++r) {
        s  += pS[r * Cout + c];
        ss += pSS[r * Cout + c];
    }
    const float inv = 1.0f / (float)NB;
    float mean = s * inv;
    float var  = ss * inv - mean * mean;
    float rs   = rsqrtf(var + 1e-5f);
    float sc   = g[c] * rs;
    scale[c] = sc;
    shift[c] = be[c] - mean * sc;
}

// ---------------- final 64 -> 2 layer ----------------------------------------
__global__ void final_kernel(const float* __restrict__ Y5, const float* __restrict__ w6,
                             const float* __restrict__ b6,
                             const float* __restrict__ scale, const float* __restrict__ shift,
                             float* __restrict__ xout)
{
    __shared__ float w[128];
    __shared__ float sc[64], sh[64];
    int tid = threadIdx.x;
    if (tid < 128) w[tid] = w6[tid];
    if (tid < 64) { sc[tid] = scale[tid]; sh[tid] = shift[tid]; }
    __syncthreads();

    int row = blockIdx.x * blockDim.x + tid;
    float a0 = 0.f, a1 = 0.f;
    const float* yr = Y5 + (size_t)row * 64;
#pragma unroll
    for (int k = 0; k < 64; k += 4) {
        float4 v = *(const float4*)(yr + k);
        float x0 = fmaxf(fmaf(v.x, sc[k + 0], sh[k + 0]), 0.f);
        float x1 = fmaxf(fmaf(v.y, sc[k + 1], sh[k + 1]), 0.f);
        float x2 = fmaxf(fmaf(v.z, sc[k + 2], sh[k + 2]), 0.f);
        float x3 = fmaxf(fmaf(v.w, sc[k + 3], sh[k + 3]), 0.f);
        a0 = fmaf(x0, w[(k + 0) * 2 + 0], a0); a1 = fmaf(x0, w[(k + 0) * 2 + 1], a1);
        a0 = fmaf(x1, w[(k + 1) * 2 + 0], a0); a1 = fmaf(x1, w[(k + 1) * 2 + 1], a1);
        a0 = fmaf(x2, w[(k + 2) * 2 + 0], a0); a1 = fmaf(x2, w[(k + 2) * 2 + 1], a1);
        a0 = fmaf(x3, w[(k + 3) * 2 + 0], a0); a1 = fmaf(x3, w[(k + 3) * 2 + 1], a1);
    }
    xout[row * 2 + 0] = a0 + b6[0];
    xout[row * 2 + 1] = a1 + b6[1];
}

// ---------------- launch ------------------------------------------------------
extern "C" void kernel_launch(void* const* d_in, const int* in_sizes, int n_in,
                              void* d_out, int out_size)
{
    const float* pos = (const float*)d_in[0];
    const float* mc  = (const float*)d_in[1];
    const float* mv  = (const float*)d_in[2];
    const float* w1 = (const float*)d_in[3];  const float* b1 = (const float*)d_in[4];
    const float* w2 = (const float*)d_in[5];  const float* b2 = (const float*)d_in[6];
    const float* w3 = (const float*)d_in[7];  const float* b3 = (const float*)d_in[8];
    const float* w4 = (const float*)d_in[9];  const float* b4 = (const float*)d_in[10];
    const float* w5 = (const float*)d_in[11]; const float* b5 = (const float*)d_in[12];
    const float* w6 = (const float*)d_in[13]; const float* b6 = (const float*)d_in[14];
    const float* g1 = (const float*)d_in[15]; const float* be1 = (const float*)d_in[16];
    const float* g2 = (const float*)d_in[17]; const float* be2 = (const float*)d_in[18];
    const float* g3 = (const float*)d_in[19]; const float* be3 = (const float*)d_in[20];
    const float* g4 = (const float*)d_in[21]; const float* be4 = (const float*)d_in[22];
    const float* g5 = (const float*)d_in[23]; const float* be5 = (const float*)d_in[24];

    float* xout    = (float*)d_out;              // [B,2]
    float* knn_out = (float*)d_out + NB * 2;     // [B,66]

    float *pA, *pB, *pX1, *pS, *pSS, *psc, *psh;
    cudaGetSymbolAddress((void**)&pA,  g_bufA);
    cudaGetSymbolAddress((void**)&pB,  g_bufB);
    cudaGetSymbolAddress((void**)&pX1, g_X1);
    cudaGetSymbolAddress((void**)&pS,  g_pS);
    cudaGetSymbolAddress((void**)&pSS, g_pSS);
    cudaGetSymbolAddress((void**)&psc, g_scale);
    cudaGetSymbolAddress((void**)&psh, g_shift);

    const int knn_smem = NM * sizeof(float4);   // 128 KB
    cudaFuncSetAttribute(knn_kernel, cudaFuncAttributeMaxDynamicSharedMemorySize, knn_smem);

    grid_zero_kernel<<<GC2 / 256, 256>>>();
    grid_count_kernel<<<NB / 256, 256>>>(pos, mc);
    grid_scan_kernel<<<1, 256>>>();
    grid_scatter_kernel<<<NB / 256, 256>>>(pos, mc);

    knn_kernel<<<NB / 256, 256, knn_smem>>>(pos, mc, mv, knn_out, pX1);

    gemm_bn<<<dim3(1, NROWBLK), 256>>>(pX1, w1, b1, nullptr, nullptr, pA, pS, pSS, 80, 66, 128, 0);
    bnstats_kernel<<<1, 128>>>(pS, pSS, g1, be1, psc, psh, 128);
    gemm_bn<<<dim3(2, NROWBLK), 256>>>(pA, w2, b2, psc, psh, pB, pS, pSS, 128, 128, 256, 1);
    bnstats_kernel<<<2, 128>>>(pS, pSS, g2, be2, psc, psh, 256);
    gemm_bn<<<dim3(4, NROWBLK), 256>>>(pB, w3, b3, psc, psh, pA, pS, pSS, 256, 256, 512, 1);
    bnstats_kernel<<<4, 128>>>(pS, pSS, g3, be3, psc, psh, 512);
    gemm_bn<<<dim3(1, NROWBLK), 256>>>(pA, w4, b4, psc, psh, pB, pS, pSS, 512, 512, 128, 1);
    bnstats_kernel<<<1, 128>>>(pS, pSS, g4, be4, psc, psh, 128);
    gemm_bn<<<dim3(1, NROWBLK), 256>>>(pB, w5, b5, psc, psh, pA, pS, pSS, 128, 128, 64, 1);
    bnstats_kernel<<<1, 128>>>(pS, pSS, g5, be5, psc, psh, 64);
    final_kernel<<<NB / 256, 256>>>(pA, w6, b6, psc, psh, xout);
}

// round 16
// speedup vs baseline: 1.5481x; 1.5481x over previous
#include <cuda_runtime.h>
#include <cstdint>
#include <cstring>

#define NB 32768
#define NM 8192
#define KNN 16
#define NROWBLK (NB / 128)
#define GD 64
#define GC2 (GD * GD)
#define GLO (-6.0f)
#define GINV 5.3333333333f     // 1 / (12/64)
#define SEEDW 128              // half-width of Morton seed window

// ---------------- scratch (device globals; no allocations allowed) ----------
__device__ float  g_bufA[NB * 512];
__device__ float  g_bufB[NB * 512];
__device__ float  g_X1[NB * 80];
__device__ float  g_pS[NROWBLK * 512];
__device__ float  g_pSS[NROWBLK * 512];
__device__ float  g_scale[512];
__device__ float  g_shift[512];
__device__ int    g_mCnt[GC2];
__device__ int    g_mCur[GC2];
__device__ int    g_qCnt[GC2];
__device__ int    g_qCur[GC2];
__device__ int    g_qperm[NB];
__device__ float4 g_mcS[NM];     // MORTON-sorted (x, y, |m|^2, orig-idx bits)

// packed f32x2 fma helpers (FFMA2)
#define FMA2(d, a, b) \
    asm("fma.rn.f32x2 %0, %1, %2, %0;" : "+l"(d) : "l"(a), "l"(b))
#define PACK2(d, s) \
    asm("mov.b64 %0, {%1, %1};" : "=l"(d) : "r"(__float_as_uint(s)))

__device__ __forceinline__ float2 unpack2(unsigned long long v) {
    float2 f; memcpy(&f, &v, 8); return f;
}

// ---------------- morton helpers ---------------------------------------------
__device__ __forceinline__ int cell_x(float x) {
    int c = (int)floorf((x - GLO) * GINV);
    return min(GD - 1, max(0, c));
}
__device__ __forceinline__ unsigned morton_part(unsigned v) {
    v &= 63u;
    v = (v | (v << 4)) & 0x0F0Fu;
    v = (v | (v << 2)) & 0x3333u;
    v = (v | (v << 1)) & 0x5555u;
    return v;
}
__device__ __forceinline__ int morton_of(float x, float y) {
    return (int)(morton_part((unsigned)cell_x(x)) |
                 (morton_part((unsigned)cell_x(y)) << 1));
}

// ---------------- build kernels ----------------------------------------------
__global__ void grid_zero_kernel() {
    int i = blockIdx.x * blockDim.x + threadIdx.x;
    if (i < GC2) { g_mCnt[i] = 0; g_qCnt[i] = 0; }
}

__global__ void grid_count_kernel(const float* __restrict__ pos,
                                  const float* __restrict__ mc) {
    int i = blockIdx.x * blockDim.x + threadIdx.x;
    if (i < NM) {
        float2 c = ((const float2*)mc)[i];
        atomicAdd(&g_mCnt[morton_of(c.x, c.y)], 1);
    }
    float2 p = ((const float2*)pos)[i];
    atomicAdd(&g_qCnt[morton_of(p.x, p.y)], 1);
}

__global__ void grid_scan_kernel() {   // 1 block, 256 threads; 16 cells/thread
    __shared__ int bs[256];
    int t = threadIdx.x;
    int base = t << 4;
    int loc[16];
    int s = 0;
#pragma unroll
    for (int k = 0; k < 16; ++k) { loc[k] = s; s += g_mCnt[base + k]; }
    bs[t] = s;
    __syncthreads();
    if (t == 0) { int a = 0; for (int i = 0; i < 256; ++i) { int c = bs[i]; bs[i] = a; a += c; } }
    __syncthreads();
#pragma unroll
    for (int k = 0; k < 16; ++k) g_mCur[base + k] = bs[t] + loc[k];
    __syncthreads();
    s = 0;
#pragma unroll
    for (int k = 0; k < 16; ++k) { loc[k] = s; s += g_qCnt[base + k]; }
    bs[t] = s;
    __syncthreads();
    if (t == 0) { int a = 0; for (int i = 0; i < 256; ++i) { int c = bs[i]; bs[i] = a; a += c; } }
    __syncthreads();
#pragma unroll
    for (int k = 0; k < 16; ++k) g_qCur[base + k] = bs[t] + loc[k];
}

__global__ void grid_scatter_kernel(const float* __restrict__ pos,
                                    const float* __restrict__ mc) {
    int i = blockIdx.x * blockDim.x + threadIdx.x;
    if (i < NM) {
        float2 c = ((const float2*)mc)[i];
        float mm = __fadd_rn(__fmul_rn(c.x, c.x), __fmul_rn(c.y, c.y));
        int slot = atomicAdd(&g_mCur[morton_of(c.x, c.y)], 1);
        g_mcS[slot] = make_float4(c.x, c.y, mm, __int_as_float(i));
    }
    float2 p = ((const float2*)pos)[i];
    int slot = atomicAdd(&g_qCur[morton_of(p.x, p.y)], 1);
    g_qperm[slot] = i;
}

// ---------------- KNN: Morton seed + 8-way pipelined dense scan --------------
// Seed window: per-point insert scan (inserts common there).
// Dense complements: groups of 8 with independent loads/d2s (MLP=8) and a
// 3-level TREE min (no serial fmin chain); one compare per group; rare rescan
// from registers. Selection = min-16 under total order (d2, idx) == stable
// lax.top_k. d2 rounding identical to the verified R6 formula.
extern __shared__ float4 knn_tile[];

__global__ void knn_kernel(const float* __restrict__ pos,
                           const float* __restrict__ mc,
                           const float* __restrict__ mv,
                           float* __restrict__ knn_out,   // [B,66]
                           float* __restrict__ x1pad)     // [B,80]
{
    const int tid = threadIdx.x;
    for (int j = tid; j < NM; j += blockDim.x) knn_tile[j] = g_mcS[j];
    __syncthreads();

    const int row = g_qperm[blockIdx.x * blockDim.x + tid];
    const float2 p = ((const float2*)pos)[row];
    const float pp = __fadd_rn(__fmul_rn(p.x, p.x), __fmul_rn(p.y, p.y));

    // warp-uniform window: binary search lane-0's Morton code in the tile
    int mcode0 = __shfl_sync(0xffffffffu, morton_of(p.x, p.y), 0);
    int lo = 0, hi = NM;
#pragma unroll
    for (int it = 0; it < 13; ++it) {
        int mid = (lo + hi) >> 1;
        float4 q = knn_tile[mid];
        int code = morton_of(q.x, q.y);
        if (code < mcode0) lo = mid + 1; else hi = mid;
    }
    const int wlo = max(0, lo - SEEDW);
    const int whi = min(NM, lo + SEEDW);

    float bd[KNN];
    int   bi[KNN];
#pragma unroll
    for (int t = 0; t < KNN; ++t) { bd[t] = 3.4e38f; bi[t] = 0x7fffffff; }

    auto d2_of = [&](float4 q) {
        float dot = __fmaf_rn(p.y, q.y, __fmul_rn(p.x, q.x));
        float s   = __fadd_rn(pp, q.z);
        return __fmaf_rn(-2.0f, dot, s);
    };

    auto insert = [&](float d2, int idx) {
        if (d2 < bd[KNN - 1] ||
            (d2 == bd[KNN - 1] && idx < bi[KNN - 1])) {
            bd[KNN - 1] = d2;
            bi[KNN - 1] = idx;
#pragma unroll
            for (int t = KNN - 1; t >= 1; --t) {
                bool sw = (bd[t] < bd[t - 1]) ||
                          (bd[t] == bd[t - 1] && bi[t] < bi[t - 1]);
                float td = bd[t]; int ti = bi[t];
                if (sw) {
                    bd[t] = bd[t - 1]; bi[t] = bi[t - 1];
                    bd[t - 1] = td;    bi[t - 1] = ti;
                }
            }
        }
    };

    // phase 1: seed window, per-point insert path
    for (int j = wlo; j < whi; ++j) {
        float4 q = knn_tile[j];
        float d2 = d2_of(q);
        if (d2 <= bd[KNN - 1]) insert(d2, __float_as_int(q.w));
    }

    // phase 2: dense complements, 8-way pipelined tree-min screening
    auto scan_dense = [&](int rlo, int rhi) {
        int j = rlo;
        for (; j + 8 <= rhi; j += 8) {
            float4 q0 = knn_tile[j + 0];
            float4 q1 = knn_tile[j + 1];
            float4 q2 = knn_tile[j + 2];
            float4 q3 = knn_tile[j + 3];
            float4 q4 = knn_tile[j + 4];
            float4 q5 = knn_tile[j + 5];
            float4 q6 = knn_tile[j + 6];
            float4 q7 = knn_tile[j + 7];
            float d0 = d2_of(q0), d1 = d2_of(q1), d2v = d2_of(q2), d3 = d2_of(q3);
            float d4 = d2_of(q4), d5 = d2_of(q5), d6 = d2_of(q6), d7 = d2_of(q7);
            float m01 = fminf(d0, d1), m23 = fminf(d2v, d3);
            float m45 = fminf(d4, d5), m67 = fminf(d6, d7);
            float gmin = fminf(fminf(m01, m23), fminf(m45, m67));
            if (gmin <= bd[KNN - 1]) {
                if (d0  <= bd[KNN - 1]) insert(d0,  __float_as_int(q0.w));
                if (d1  <= bd[KNN - 1]) insert(d1,  __float_as_int(q1.w));
                if (d2v <= bd[KNN - 1]) insert(d2v, __float_as_int(q2.w));
                if (d3  <= bd[KNN - 1]) insert(d3,  __float_as_int(q3.w));
                if (d4  <= bd[KNN - 1]) insert(d4,  __float_as_int(q4.w));
                if (d5  <= bd[KNN - 1]) insert(d5,  __float_as_int(q5.w));
                if (d6  <= bd[KNN - 1]) insert(d6,  __float_as_int(q6.w));
                if (d7  <= bd[KNN - 1]) insert(d7,  __float_as_int(q7.w));
            }
        }
        for (; j < rhi; ++j) {
            float4 q = knn_tile[j];
            float d2 = d2_of(q);
            if (d2 <= bd[KNN - 1]) insert(d2, __float_as_int(q.w));
        }
    };
    scan_dense(0, wlo);
    scan_dense(whi, NM);

    float* o1 = knn_out + (size_t)row * 66;
    float* o2 = x1pad + (size_t)row * 80;
    o1[0] = p.x; o1[1] = p.y;
    o2[0] = p.x; o2[1] = p.y;
#pragma unroll
    for (int t = 0; t < KNN; ++t) {
        int i = bi[t];
        float2 c = ((const float2*)mc)[i];
        float2 v = ((const float2*)mv)[i];
        int base = 2 + 4 * t;
        o1[base + 0] = c.x; o1[base + 1] = c.y; o1[base + 2] = v.x; o1[base + 3] = v.y;
        o2[base + 0] = c.x; o2[base + 1] = c.y; o2[base + 2] = v.x; o2[base + 3] = v.y;
    }
#pragma unroll
    for (int t = 66; t < 80; ++t) o2[t] = 0.0f;
}

// ---------------- GEMM: FFMA2 row-pair packed (R12, proven) ------------------
__global__ __launch_bounds__(256, 2)
void gemm_bn(const float* __restrict__ X, const float* __restrict__ W,
             const float* __restrict__ bias,
             const float* __restrict__ scale, const float* __restrict__ shift,
             float* __restrict__ Y, float* __restrict__ pS, float* __restrict__ pSS,
             int CinX, int CinW, int Cout, int useBN)
{
    __shared__ float As[16][132];
    __shared__ float Bs[16][128];
    __shared__ float sRed[16][128];

    const int tid = threadIdx.x;
    const int tx = tid & 15, ty = tid >> 4;
    const int n0 = blockIdx.x << 7;
    const int m0 = blockIdx.y << 7;

    unsigned long long acc[4][8];
#pragma unroll
    for (int r = 0; r < 4; ++r)
#pragma unroll
        for (int c = 0; c < 8; ++c) acc[r][c] = 0ull;

    const int nkt = CinX >> 4;
    for (int kt = 0; kt < nkt; ++kt) {
        const int k0 = kt << 4;
#pragma unroll
        for (int i = 0; i < 2; ++i) {
            int idx = tid + (i << 8);
            int r = idx >> 2, c4 = idx & 3;
            const float* xp = X + (size_t)(m0 + r) * CinX + k0 + (c4 << 2);
            float4 v = *(const float4*)xp;
            if (useBN) {
                float4 sc = *(const float4*)(scale + k0 + (c4 << 2));
                float4 sh = *(const float4*)(shift + k0 + (c4 << 2));
                v.x = fmaxf(fmaf(v.x, sc.x, sh.x), 0.0f);
                v.y = fmaxf(fmaf(v.y, sc.y, sh.y), 0.0f);
                v.z = fmaxf(fmaf(v.z, sc.z, sh.z), 0.0f);
                v.w = fmaxf(fmaf(v.w, sc.w, sh.w), 0.0f);
            }
            As[(c4 << 2) + 0][r] = v.x;
            As[(c4 << 2) + 1][r] = v.y;
            As[(c4 << 2) + 2][r] = v.z;
            As[(c4 << 2) + 3][r] = v.w;
        }
#pragma unroll
        for (int i = 0; i < 2; ++i) {
            int idx = tid + (i << 8);
            int kr = idx >> 5, c = idx & 31;
            int krow = k0 + kr, col = n0 + (c << 2);
            float4 v = make_float4(0.f, 0.f, 0.f, 0.f);
            if (krow < CinW && col < Cout)
                v = *(const float4*)(W + (size_t)krow * Cout + col);
            *(float4*)&Bs[kr][c << 2] = v;
        }
        __syncthreads();
#pragma unroll
        for (int kk = 0; kk < 16; ++kk) {
            ulonglong2 A0 = *(const ulonglong2*)&As[kk][ty << 2];
            ulonglong2 A1 = *(const ulonglong2*)&As[kk][64 + (ty << 2)];
            unsigned long long ap[4] = {A0.x, A0.y, A1.x, A1.y};
            float4 b0 = *(const float4*)&Bs[kk][tx << 2];
            float4 b1 = *(const float4*)&Bs[kk][64 + (tx << 2)];
            unsigned long long bp[8];
            PACK2(bp[0], b0.x); PACK2(bp[1], b0.y);
            PACK2(bp[2], b0.z); PACK2(bp[3], b0.w);
            PACK2(bp[4], b1.x); PACK2(bp[5], b1.y);
            PACK2(bp[6], b1.z); PACK2(bp[7], b1.w);
#pragma unroll
            for (int r = 0; r < 4; ++r)
#pragma unroll
                for (int c = 0; c < 8; ++c) FMA2(acc[r][c], ap[r], bp[c]);
        }
        __syncthreads();
    }

    float csum[8], csq[8];
#pragma unroll
    for (int c = 0; c < 8; ++c) { csum[c] = 0.f; csq[c] = 0.f; }

#pragma unroll
    for (int rr = 0; rr < 8; ++rr) {
        int rloc = (rr < 4) ? ((ty << 2) + rr) : (64 + (ty << 2) + rr - 4);
        int row = m0 + rloc;
        const int rp = rr >> 1;
        const bool hi = (rr & 1) != 0;
#pragma unroll
        for (int g2 = 0; g2 < 2; ++g2) {
            int colloc = (g2 << 6) + (tx << 2);
            int col = n0 + colloc;
            if (col < Cout) {
                float2 q0 = unpack2(acc[rp][g2 * 4 + 0]);
                float2 q1 = unpack2(acc[rp][g2 * 4 + 1]);
                float2 q2 = unpack2(acc[rp][g2 * 4 + 2]);
                float2 q3 = unpack2(acc[rp][g2 * 4 + 3]);
                float4 bb = *(const float4*)(bias + col);
                float4 o;
                o.x = (hi ? q0.y : q0.x) + bb.x;
                o.y = (hi ? q1.y : q1.x) + bb.y;
                o.z = (hi ? q2.y : q2.x) + bb.z;
                o.w = (hi ? q3.y : q3.x) + bb.w;
                *(float4*)(Y + (size_t)row * Cout + col) = o;
                csum[g2 * 4 + 0] += o.x; csq[g2 * 4 + 0] += o.x * o.x;
                csum[g2 * 4 + 1] += o.y; csq[g2 * 4 + 1] += o.y * o.y;
                csum[g2 * 4 + 2] += o.z; csq[g2 * 4 + 2] += o.z * o.z;
                csum[g2 * 4 + 3] += o.w; csq[g2 * 4 + 3] += o.w * o.w;
            }
        }
    }

    *(float4*)&sRed[ty][tx << 2]        = make_float4(csum[0], csum[1], csum[2], csum[3]);
    *(float4*)&sRed[ty][64 + (tx << 2)] = make_float4(csum[4], csum[5], csum[6], csum[7]);
    __syncthreads();
    if (tid < 128) {
        float s = 0.f;
#pragma unroll
        for (int t = 0; t < 16; ++t) s += sRed[t][tid];
        if (n0 + tid < Cout) pS[blockIdx.y * Cout + n0 + tid] = s;
    }
    __syncthreads();
    *(float4*)&sRed[ty][tx << 2]        = make_float4(csq[0], csq[1], csq[2], csq[3]);
    *(float4*)&sRed[ty][64 + (tx << 2)] = make_float4(csq[4], csq[5], csq[6], csq[7]);
    __syncthreads();
    if (tid < 128) {
        float s = 0.f;
#pragma unroll
        for (int t = 0; t < 16; ++t) s += sRed[t][tid];
        if (n0 + tid < Cout) pSS[blockIdx.y * Cout + n0 + tid] = s;
    }
}

// ---------------- BN stats fold ----------------------------------------------
__global__ void bnstats_kernel(const float* __restrict__ pS, const float* __restrict__ pSS,
                               const float* __restrict__ g, const float* __restrict__ be,
                               float* __restrict__ scale, float* __restrict__ shift, int Cout)
{
    int c = blockIdx.x * blockDim.x + threadIdx.x;
    if (c >= Cout) return;
    float s = 0.f, ss = 0.f;
    for (int r = 0; r < NROWBLK; ++r) {
        s  += pS[r * Cout + c];
        ss += pSS[r * Cout + c];
    }
    const float inv = 1.0f / (float)NB;
    float mean = s * inv;
    float var  = ss * inv - mean * mean;
    float rs   = rsqrtf(var + 1e-5f);
    float sc   = g[c] * rs;
    scale[c] = sc;
    shift[c] = be[c] - mean * sc;
}

// ---------------- final 64 -> 2 layer ----------------------------------------
__global__ void final_kernel(const float* __restrict__ Y5, const float* __restrict__ w6,
                             const float* __restrict__ b6,
                             const float* __restrict__ scale, const float* __restrict__ shift,
                             float* __restrict__ xout)
{
    __shared__ float w[128];
    __shared__ float sc[64], sh[64];
    int tid = threadIdx.x;
    if (tid < 128) w[tid] = w6[tid];
    if (tid < 64) { sc[tid] = scale[tid]; sh[tid] = shift[tid]; }
    __syncthreads();

    int row = blockIdx.x * blockDim.x + tid;
    float a0 = 0.f, a1 = 0.f;
    const float* yr = Y5 + (size_t)row * 64;
#pragma unroll
    for (int k = 0; k < 64; k += 4) {
        float4 v = *(const float4*)(yr + k);
        float x0 = fmaxf(fmaf(v.x, sc[k + 0], sh[k + 0]), 0.f);
        float x1 = fmaxf(fmaf(v.y, sc[k + 1], sh[k + 1]), 0.f);
        float x2 = fmaxf(fmaf(v.z, sc[k + 2], sh[k + 2]), 0.f);
        float x3 = fmaxf(fmaf(v.w, sc[k + 3], sh[k + 3]), 0.f);
        a0 = fmaf(x0, w[(k + 0) * 2 + 0], a0); a1 = fmaf(x0, w[(k + 0) * 2 + 1], a1);
        a0 = fmaf(x1, w[(k + 1) * 2 + 0], a0); a1 = fmaf(x1, w[(k + 1) * 2 + 1], a1);
        a0 = fmaf(x2, w[(k + 2) * 2 + 0], a0); a1 = fmaf(x2, w[(k + 2) * 2 + 1], a1);
        a0 = fmaf(x3, w[(k + 3) * 2 + 0], a0); a1 = fmaf(x3, w[(k + 3) * 2 + 1], a1);
    }
    xout[row * 2 + 0] = a0 + b6[0];
    xout[row * 2 + 1] = a1 + b6[1];
}

// ---------------- launch ------------------------------------------------------
extern "C" void kernel_launch(void* const* d_in, const int* in_sizes, int n_in,
                              void* d_out, int out_size)
{
    const float* pos = (const float*)d_in[0];
    const float* mc  = (const float*)d_in[1];
    const float* mv  = (const float*)d_in[2];
    const float* w1 = (const float*)d_in[3];  const float* b1 = (const float*)d_in[4];
    const float* w2 = (const float*)d_in[5];  const float* b2 = (const float*)d_in[6];
    const float* w3 = (const float*)d_in[7];  const float* b3 = (const float*)d_in[8];
    const float* w4 = (const float*)d_in[9];  const float* b4 = (const float*)d_in[10];
    const float* w5 = (const float*)d_in[11]; const float* b5 = (const float*)d_in[12];
    const float* w6 = (const float*)d_in[13]; const float* b6 = (const float*)d_in[14];
    const float* g1 = (const float*)d_in[15]; const float* be1 = (const float*)d_in[16];
    const float* g2 = (const float*)d_in[17]; const float* be2 = (const float*)d_in[18];
    const float* g3 = (const float*)d_in[19]; const float* be3 = (const float*)d_in[20];
    const float* g4 = (const float*)d_in[21]; const float* be4 = (const float*)d_in[22];
    const float* g5 = (const float*)d_in[23]; const float* be5 = (const float*)d_in[24];

    float* xout    = (float*)d_out;              // [B,2]
    float* knn_out = (float*)d_out + NB * 2;     // [B,66]

    float *pA, *pB, *pX1, *pS, *pSS, *psc, *psh;
    cudaGetSymbolAddress((void**)&pA,  g_bufA);
    cudaGetSymbolAddress((void**)&pB,  g_bufB);
    cudaGetSymbolAddress((void**)&pX1, g_X1);
    cudaGetSymbolAddress((void**)&pS,  g_pS);
    cudaGetSymbolAddress((void**)&pSS, g_pSS);
    cudaGetSymbolAddress((void**)&psc, g_scale);
    cudaGetSymbolAddress((void**)&psh, g_shift);

    const int knn_smem = NM * sizeof(float4);   // 128 KB
    cudaFuncSetAttribute(knn_kernel, cudaFuncAttributeMaxDynamicSharedMemorySize, knn_smem);

    grid_zero_kernel<<<GC2 / 256, 256>>>();
    grid_count_kernel<<<NB / 256, 256>>>(pos, mc);
    grid_scan_kernel<<<1, 256>>>();
    grid_scatter_kernel<<<NB / 256, 256>>>(pos, mc);

    knn_kernel<<<NB / 256, 256, knn_smem>>>(pos, mc, mv, knn_out, pX1);

    gemm_bn<<<dim3(1, NROWBLK), 256>>>(pX1, w1, b1, nullptr, nullptr, pA, pS, pSS, 80, 66, 128, 0);
    bnstats_kernel<<<1, 128>>>(pS, pSS, g1, be1, psc, psh, 128);
    gemm_bn<<<dim3(2, NROWBLK), 256>>>(pA, w2, b2, psc, psh, pB, pS, pSS, 128, 128, 256, 1);
    bnstats_kernel<<<2, 128>>>(pS, pSS, g2, be2, psc, psh, 256);
    gemm_bn<<<dim3(4, NROWBLK), 256>>>(pB, w3, b3, psc, psh, pA, pS, pSS, 256, 256, 512, 1);
    bnstats_kernel<<<4, 128>>>(pS, pSS, g3, be3, psc, psh, 512);
    gemm_bn<<<dim3(1, NROWBLK), 256>>>(pA, w4, b4, psc, psh, pB, pS, pSS, 512, 512, 128, 1);
    bnstats_kernel<<<1, 128>>>(pS, pSS, g4, be4, psc, psh, 128);
    gemm_bn<<<dim3(1, NROWBLK), 256>>>(pB, w5, b5, psc, psh, pA, pS, pSS, 128, 128, 64, 1);
    bnstats_kernel<<<1, 128>>>(pS, pSS, g5, be5, psc, psh, 64);
    final_kernel<<<NB / 256, 256>>>(pA, w6, b6, psc, psh, xout);
}